// round 3
// baseline (speedup 1.0000x reference)
#include <cuda_runtime.h>
#include <cstdint>
#include <cstddef>

// ---------------- static problem config ----------------
#define IMG    56
#define WIN    7
#define SHIFTS 3
#define CDIM   256
#define NHEAD  8
#define DHEAD  32
#define SWIN   49          // tokens per window
#define NYW    8           // windows per side
#define NWIN   64          // windows per image
#define NMLP   1024
#define BATCH  32
#define NTOK   (BATCH*IMG*IMG)   // 100352
#define QSCALE 0.17677669529663689f   // 32^-0.5

// ---------------- scratch (device globals; no runtime allocation) ----------------
__device__ float g_xn[(size_t)NTOK * CDIM];   // LN output (reused for both LNs)
__device__ float g_x1[(size_t)NTOK * CDIM];   // x + attention output
__device__ float g_h [(size_t)NTOK * NMLP];   // MLP hidden

// ---------------- packed f32x2 helpers (Blackwell FFMA2) ----------------
typedef unsigned long long u64t;

__device__ __forceinline__ u64t pk2(float x, float y) {
    u64t r;
    asm("mov.b64 %0, {%1, %2};" : "=l"(r) : "f"(x), "f"(y));
    return r;
}
__device__ __forceinline__ float2 up2(u64t v) {
    float2 r;
    asm("mov.b64 {%0, %1}, %2;" : "=f"(r.x), "=f"(r.y) : "l"(v));
    return r;
}
__device__ __forceinline__ void fma2(u64t& d, u64t a, u64t b) {
#if __CUDA_ARCH__ >= 1000
    asm("fma.rn.f32x2 %0, %1, %2, %0;" : "+l"(d) : "l"(a), "l"(b));
#else
    float2 dd = up2(d), aa = up2(a), bb = up2(b);
    dd.x = fmaf(aa.x, bb.x, dd.x);
    dd.y = fmaf(aa.y, bb.y, dd.y);
    d = pk2(dd.x, dd.y);
#endif
}

__device__ __forceinline__ float gelu_exact(float v) {
    return 0.5f * v * (1.0f + erff(v * 0.70710678118654752f));
}

// ---------------- LayerNorm: one warp per token ----------------
__global__ __launch_bounds__(256) void ln_kernel(
    const float* __restrict__ x,
    const float* __restrict__ gamma,
    const float* __restrict__ beta,
    float* __restrict__ out)
{
    int lane = threadIdx.x & 31;
    int warp = threadIdx.x >> 5;
    int tok  = blockIdx.x * 8 + warp;

    const float4* px = (const float4*)(x + (size_t)tok * CDIM);
    float4 v0 = px[lane];
    float4 v1 = px[lane + 32];

    float s  = v0.x + v0.y + v0.z + v0.w + v1.x + v1.y + v1.z + v1.w;
    float ss = v0.x*v0.x + v0.y*v0.y + v0.z*v0.z + v0.w*v0.w
             + v1.x*v1.x + v1.y*v1.y + v1.z*v1.z + v1.w*v1.w;
    #pragma unroll
    for (int o = 16; o; o >>= 1) {
        s  += __shfl_xor_sync(0xffffffffu, s,  o);
        ss += __shfl_xor_sync(0xffffffffu, ss, o);
    }
    float mu  = s * (1.0f / 256.0f);
    float var = ss * (1.0f / 256.0f) - mu * mu;
    float rs  = rsqrtf(var + 1e-5f);

    const float4* pg = (const float4*)gamma;
    const float4* pb = (const float4*)beta;
    float4 g0 = pg[lane], g1 = pg[lane + 32];
    float4 b0 = pb[lane], b1 = pb[lane + 32];

    v0.x = (v0.x - mu) * rs * g0.x + b0.x;
    v0.y = (v0.y - mu) * rs * g0.y + b0.y;
    v0.z = (v0.z - mu) * rs * g0.z + b0.z;
    v0.w = (v0.w - mu) * rs * g0.w + b0.w;
    v1.x = (v1.x - mu) * rs * g1.x + b1.x;
    v1.y = (v1.y - mu) * rs * g1.y + b1.y;
    v1.z = (v1.z - mu) * rs * g1.z + b1.z;
    v1.w = (v1.w - mu) * rs * g1.w + b1.w;

    float4* po = (float4*)(out + (size_t)tok * CDIM);
    po[lane]      = v0;
    po[lane + 32] = v1;
}

// ---------------- fused shifted-window attention: one CTA per window ----------------
// smem layout (floats):
//   xs  [49*256]       gathered LN'd tokens; later reused as attention output o
//   qs  [8*49*33]      per-head q (padded rows, conflict-free)
//   ks  [8*49*33]
//   vs  [8*49*33]
//   att [49*52]        per-head softmaxed attention (rows owned per-warp)
//   tsrc[49] regid[49] (ints)
#define QKVPAD   33
#define ATTPAD   52
#define SM_XS    0
#define SM_QS    (SWIN*CDIM)
#define SM_KS    (SM_QS + NHEAD*SWIN*QKVPAD)
#define SM_VS    (SM_KS + NHEAD*SWIN*QKVPAD)
#define SM_ATT   (SM_VS + NHEAD*SWIN*QKVPAD)
#define SM_INTS  (SM_ATT + SWIN*ATTPAD)
#define ATT_SMEM ((SM_INTS + 2*SWIN) * 4)

__global__ __launch_bounds__(256) void attn_kernel(
    const float* __restrict__ xn,     // LN output [NTOK, C]
    const float* __restrict__ x,      // original input (residual)
    const float* __restrict__ qkv_w,  // [C, 3C]
    const float* __restrict__ qkv_b,  // [3C]
    const float* __restrict__ proj_w, // [C, C]
    const float* __restrict__ proj_b, // [C]
    const float* __restrict__ btab,   // [169, 8]
    float* __restrict__ x1)           // out: x + attn
{
    extern __shared__ float sm[];
    float* xs  = sm + SM_XS;
    float* qs  = sm + SM_QS;
    float* ks  = sm + SM_KS;
    float* vs  = sm + SM_VS;
    float* att = sm + SM_ATT;
    int* tsrc  = (int*)(sm + SM_INTS);
    int* regid = tsrc + SWIN;

    const int tid  = threadIdx.x;
    const int lane = tid & 31;
    const int w    = tid >> 5;

    const int win = blockIdx.x;
    const int b   = win >> 6;
    const int wq  = win & 63;
    const int wy  = wq >> 3;
    const int wx  = wq & 7;

    // token source index (gather==scatter map through roll) + mask region id
    if (tid < SWIN) {
        int i = tid / 7, j = tid - i * 7;
        int y  = wy * 7 + i;
        int xx = wx * 7 + j;
        int y0 = y  + SHIFTS; if (y0 >= IMG) y0 -= IMG;
        int x0 = xx + SHIFTS; if (x0 >= IMG) x0 -= IMG;
        tsrc[tid] = b * (IMG * IMG) + y0 * IMG + x0;
        // faithful mask regions: cols 49..52 were never written (stay 0)
        int rc = (y <= 48) ? 0 : ((y <= 52) ? 1 : 2);
        regid[tid] = (xx <= 48) ? rc * 3 : ((xx >= 53) ? rc * 3 + 2 : 0);
    }
    __syncthreads();

    // gather window tokens (rows strided by warp, float4 coalesced)
    for (int s = w; s < SWIN; s += 8) {
        const float4* src = (const float4*)(xn + (size_t)tsrc[s] * CDIM);
        float4* dst = (float4*)(xs + s * CDIM);
        dst[lane]      = src[lane];
        dst[lane + 32] = src[lane + 32];
    }
    __syncthreads();

    // row index per warp: s = w + 8*i (i<7), clamp invalid to 48 (discarded)
    int soff[7];
    #pragma unroll
    for (int i = 0; i < 7; i++) {
        int s = w + 8 * i; if (s > 48) s = 48;
        soff[i] = s * CDIM;
    }

    // ---------- QKV GEMM: 49x256 @ 256x768, FFMA2-packed over head pairs ----------
    for (int nb = 0; nb < 3; nb++) {
        u64t acc[7][4] = {};
        const float* wbase = qkv_w + nb * CDIM + lane;
        #pragma unroll 2
        for (int c = 0; c < CDIM; c++) {
            const float* wr = wbase + c * (3 * CDIM);
            float w0 = wr[0],   w1v = wr[32],  w2 = wr[64],  w3 = wr[96];
            float w4 = wr[128], w5  = wr[160], w6 = wr[192], w7 = wr[224];
            u64t bp0 = pk2(w0, w1v), bp1 = pk2(w2, w3);
            u64t bp2 = pk2(w4, w5),  bp3 = pk2(w6, w7);
            #pragma unroll
            for (int i = 0; i < 7; i++) {
                float xv = xs[soff[i] + c];
                u64t a = pk2(xv, xv);
                fma2(acc[i][0], a, bp0);
                fma2(acc[i][1], a, bp1);
                fma2(acc[i][2], a, bp2);
                fma2(acc[i][3], a, bp3);
            }
        }
        float scale = (nb == 0) ? QSCALE : 1.0f;
        float* dst = (nb == 0) ? qs : ((nb == 1) ? ks : vs);
        #pragma unroll
        for (int i = 0; i < 7; i++) {
            int s = w + 8 * i;
            if (s >= SWIN) break;
            #pragma unroll
            for (int p = 0; p < 4; p++) {
                float2 v = up2(acc[i][p]);
                int h0 = 2 * p, h1 = 2 * p + 1;
                float bb0 = qkv_b[nb * CDIM + h0 * 32 + lane];
                float bb1 = qkv_b[nb * CDIM + h1 * 32 + lane];
                dst[h0 * (SWIN * QKVPAD) + s * QKVPAD + lane] = (v.x + bb0) * scale;
                dst[h1 * (SWIN * QKVPAD) + s * QKVPAD + lane] = (v.y + bb1) * scale;
            }
        }
    }
    __syncthreads();

    // ---------- per-head attention (rows owned per warp -> no block syncs) ----------
    int arow[7];
    #pragma unroll
    for (int i = 0; i < 7; i++) {
        int s = w + 8 * i; if (s > 48) s = 48;
        arow[i] = s * ATTPAD;
    }

    for (int h = 0; h < NHEAD; h++) {
        const float* qh = qs + h * (SWIN * QKVPAD);
        const float* kh = ks + h * (SWIN * QKVPAD);
        const float* vh = vs + h * (SWIN * QKVPAD);

        // scores + bias + mask + softmax, one row per (warp,i)
        #pragma unroll
        for (int i = 0; i < 7; i++) {
            int s = w + 8 * i;
            if (s >= SWIN) break;
            int t1 = lane;
            int t2 = lane + 32;
            bool v2 = (t2 < SWIN);
            int t2c = v2 ? t2 : 48;
            float a1 = 0.f, a2 = 0.f;
            #pragma unroll
            for (int d = 0; d < DHEAD; d++) {
                float qv = qh[s * QKVPAD + d];
                a1 += qv * kh[t1  * QKVPAD + d];
                a2 += qv * kh[t2c * QKVPAD + d];
            }
            int i1 = s / 7, j1 = s - i1 * 7;
            {
                int it = t1 / 7, jt = t1 - it * 7;
                int ridx = (i1 - it + 6) * 13 + (j1 - jt + 6);
                a1 += btab[ridx * NHEAD + h];
                if (regid[s] != regid[t1]) a1 -= 100.0f;
            }
            if (v2) {
                int it = t2 / 7, jt = t2 - it * 7;
                int ridx = (i1 - it + 6) * 13 + (j1 - jt + 6);
                a2 += btab[ridx * NHEAD + h];
                if (regid[s] != regid[t2]) a2 -= 100.0f;
            } else {
                a2 = -1e30f;
            }
            // warp softmax over 49 scores
            float m = fmaxf(a1, a2);
            #pragma unroll
            for (int o = 16; o; o >>= 1) m = fmaxf(m, __shfl_xor_sync(0xffffffffu, m, o));
            float e1 = __expf(a1 - m);
            float e2 = v2 ? __expf(a2 - m) : 0.0f;
            float sum = e1 + e2;
            #pragma unroll
            for (int o = 16; o; o >>= 1) sum += __shfl_xor_sync(0xffffffffu, sum, o);
            float inv = 1.0f / sum;
            att[s * ATTPAD + t1] = e1 * inv;
            if (v2) att[s * ATTPAD + t2] = e2 * inv;
        }
        __syncwarp();

        // o = att @ v for this warp's rows  (t outer amortizes the v load)
        {
            float oacc[7] = {0.f, 0.f, 0.f, 0.f, 0.f, 0.f, 0.f};
            for (int t = 0; t < SWIN; t++) {
                float vv = vh[t * QKVPAD + lane];
                #pragma unroll
                for (int i = 0; i < 7; i++)
                    oacc[i] += att[arow[i] + t] * vv;
            }
            #pragma unroll
            for (int i = 0; i < 7; i++) {
                int s = w + 8 * i;
                if (s < SWIN) xs[s * CDIM + h * 32 + lane] = oacc[i];  // o overlays xs
            }
        }
        __syncwarp();
    }
    __syncthreads();

    // ---------- proj: 49x256 @ 256x256, + residual, scatter to unshifted pos ----------
    {
        u64t pacc[7][4] = {};
        const float* pwb = proj_w + lane;
        #pragma unroll 2
        for (int c = 0; c < CDIM; c++) {
            const float* wr = pwb + c * CDIM;
            float w0 = wr[0],   w1v = wr[32],  w2 = wr[64],  w3 = wr[96];
            float w4 = wr[128], w5  = wr[160], w6 = wr[192], w7 = wr[224];
            u64t bp0 = pk2(w0, w1v), bp1 = pk2(w2, w3);
            u64t bp2 = pk2(w4, w5),  bp3 = pk2(w6, w7);
            #pragma unroll
            for (int i = 0; i < 7; i++) {
                float ov = xs[soff[i] + c];
                u64t a = pk2(ov, ov);
                fma2(pacc[i][0], a, bp0);
                fma2(pacc[i][1], a, bp1);
                fma2(pacc[i][2], a, bp2);
                fma2(pacc[i][3], a, bp3);
            }
        }
        #pragma unroll
        for (int i = 0; i < 7; i++) {
            int s = w + 8 * i;
            if (s >= SWIN) break;
            int g = tsrc[s];
            const float* xrow = x  + (size_t)g * CDIM;
            float*       orow = x1 + (size_t)g * CDIM;
            #pragma unroll
            for (int p = 0; p < 4; p++) {
                float2 v = up2(pacc[i][p]);
                int c0 = (2 * p) * 32 + lane;
                int c1 = (2 * p + 1) * 32 + lane;
                orow[c0] = xrow[c0] + v.x + proj_b[c0];
                orow[c1] = xrow[c1] + v.y + proj_b[c1];
            }
        }
    }
}

// ---------------- tiled SGEMM (128x128x16, 8x8 microtile via FFMA2) ----------------
// EPI==0: out = gelu(A@W + bias)
// EPI==1: out = res + A@W + bias
template<int EPI>
__global__ __launch_bounds__(256, 2) void gemm_kernel(
    const float* __restrict__ A,     // [M, K]
    const float* __restrict__ W,     // [K, N]
    const float* __restrict__ bias,  // [N]
    const float* __restrict__ res,   // [M, N] (EPI==1)
    float* __restrict__ out,         // [M, N]
    int M, int N, int K)
{
    __shared__ float As[16][132];
    __shared__ float Bs[16][128];

    const int tid = threadIdx.x;
    const int tm = tid >> 4;        // 0..15
    const int tn = tid & 15;        // 0..15
    const int row0 = blockIdx.y * 128;
    const int col0 = blockIdx.x * 128;

    u64t acc[4][8] = {};            // 4 row-pairs x 8 cols

    const int arow = tid >> 2;              // 0..63
    const int ak4  = (tid & 3) << 2;        // 0,4,8,12
    const int bk   = tid >> 5;              // 0..7
    const int bc4  = (tid & 31) << 2;       // 0..124

    const float* Ap = A + (size_t)(row0 + arow) * K + ak4;
    const float* Wp = W + (size_t)bk * N + col0 + bc4;

    for (int kt = 0; kt < K; kt += 16) {
        float4 a0 = *(const float4*)(Ap + kt);
        float4 a1 = *(const float4*)(Ap + (size_t)64 * K + kt);
        float4 b0 = *(const float4*)(Wp + (size_t)kt * N);
        float4 b1 = *(const float4*)(Wp + (size_t)(kt + 8) * N);
        __syncthreads();
        As[ak4 + 0][arow] = a0.x; As[ak4 + 1][arow] = a0.y;
        As[ak4 + 2][arow] = a0.z; As[ak4 + 3][arow] = a0.w;
        As[ak4 + 0][arow + 64] = a1.x; As[ak4 + 1][arow + 64] = a1.y;
        As[ak4 + 2][arow + 64] = a1.z; As[ak4 + 3][arow + 64] = a1.w;
        *(float4*)&Bs[bk][bc4]     = b0;
        *(float4*)&Bs[bk + 8][bc4] = b1;
        __syncthreads();
        #pragma unroll
        for (int k = 0; k < 16; k++) {
            float4 af0 = *(const float4*)&As[k][tm * 4];
            float4 af1 = *(const float4*)&As[k][64 + tm * 4];
            float4 bf0 = *(const float4*)&Bs[k][tn * 4];
            float4 bf1 = *(const float4*)&Bs[k][64 + tn * 4];
            u64t ap[4] = { pk2(af0.x, af0.y), pk2(af0.z, af0.w),
                           pk2(af1.x, af1.y), pk2(af1.z, af1.w) };
            float bsv[8] = { bf0.x, bf0.y, bf0.z, bf0.w,
                             bf1.x, bf1.y, bf1.z, bf1.w };
            #pragma unroll
            for (int c = 0; c < 8; c++) {
                u64t bd = pk2(bsv[c], bsv[c]);
                #pragma unroll
                for (int rp = 0; rp < 4; rp++) fma2(acc[rp][c], ap[rp], bd);
            }
        }
    }

    // epilogue: rows per pair rp -> {base, base+1}; float4 stores
    #pragma unroll
    for (int rp = 0; rp < 4; rp++) {
        int rbase = row0 + tm * 4 + (rp >> 1) * 64 + (rp & 1) * 2;
        #pragma unroll
        for (int dd = 0; dd < 2; dd++) {
            int row = rbase + dd;
            #pragma unroll
            for (int half = 0; half < 2; half++) {
                int cb = col0 + half * 64 + tn * 4;
                float vals[4];
                #pragma unroll
                for (int l = 0; l < 4; l++) {
                    float2 t = up2(acc[rp][half * 4 + l]);
                    float a = (dd == 0) ? t.x : t.y;
                    a += bias[cb + l];
                    if (EPI == 0) a = gelu_exact(a);
                    else          a += res[(size_t)row * N + cb + l];
                    vals[l] = a;
                }
                *(float4*)(out + (size_t)row * N + cb) =
                    make_float4(vals[0], vals[1], vals[2], vals[3]);
            }
        }
    }
}

// ---------------- launch ----------------
extern "C" void kernel_launch(void* const* d_in, const int* in_sizes, int n_in,
                              void* d_out, int out_size)
{
    const float* x      = (const float*)d_in[0];
    const float* gamma  = (const float*)d_in[1];
    const float* beta   = (const float*)d_in[2];
    const float* qkv_w  = (const float*)d_in[3];
    const float* qkv_b  = (const float*)d_in[4];
    const float* proj_w = (const float*)d_in[5];
    const float* proj_b = (const float*)d_in[6];
    const float* btab   = (const float*)d_in[7];
    const float* w1     = (const float*)d_in[8];
    const float* b1     = (const float*)d_in[9];
    const float* w2     = (const float*)d_in[10];
    const float* b2     = (const float*)d_in[11];
    float* out = (float*)d_out;

    float *xn, *x1, *hbuf;
    cudaGetSymbolAddress((void**)&xn,   g_xn);
    cudaGetSymbolAddress((void**)&x1,   g_x1);
    cudaGetSymbolAddress((void**)&hbuf, g_h);

    cudaFuncSetAttribute(attn_kernel,
                         cudaFuncAttributeMaxDynamicSharedMemorySize, ATT_SMEM);

    // 1) LN(x) -> xn
    ln_kernel<<<NTOK / 8, 256>>>(x, gamma, beta, xn);
    // 2) fused shifted-window attention + proj + residual -> x1
    attn_kernel<<<BATCH * NWIN, 256, ATT_SMEM>>>(xn, x, qkv_w, qkv_b,
                                                 proj_w, proj_b, btab, x1);
    // 3) LN(x1) -> xn
    ln_kernel<<<NTOK / 8, 256>>>(x1, gamma, beta, xn);
    // 4) h = gelu(xn @ w1 + b1)
    gemm_kernel<0><<<dim3(NMLP / 128, NTOK / 128), 256>>>(xn, w1, b1, x1, hbuf,
                                                          NTOK, NMLP, CDIM);
    // 5) out = x1 + h @ w2 + b2
    gemm_kernel<1><<<dim3(CDIM / 128, NTOK / 128), 256>>>(hbuf, w2, b2, x1, out,
                                                          NTOK, CDIM, NMLP);
}

// round 4
// speedup vs baseline: 1.1413x; 1.1413x over previous
#include <cuda_runtime.h>
#include <cstdint>
#include <cstddef>

// ---------------- static problem config ----------------
#define IMG    56
#define WIN    7
#define SHIFTS 3
#define CDIM   256
#define NHEAD  8
#define DHEAD  32
#define SWIN   49
#define NWIN   64
#define NMLP   1024
#define BATCH  32
#define NTOK   (BATCH*IMG*IMG)           // 100352
#define QSCALE 0.17677669529663689f

// ---------------- scratch (device globals) ----------------
__device__ float g_xn  [(size_t)NTOK * CDIM];      // LN1 out; later o (attn out)
__device__ float g_x1  [(size_t)NTOK * CDIM];      // x + attn
__device__ float g_qkv [(size_t)NTOK * 3 * CDIM];  // qkv; later LN2 out (first 256 cols worth reused separately)
__device__ float g_xn2 [(size_t)NTOK * CDIM];      // LN2 out
__device__ float g_h   [(size_t)NTOK * NMLP];      // MLP hidden

// ---------------- packed f32x2 helpers ----------------
typedef unsigned long long u64t;

__device__ __forceinline__ u64t pk2(float x, float y) {
    u64t r;
    asm("mov.b64 %0, {%1, %2};" : "=l"(r) : "f"(x), "f"(y));
    return r;
}
__device__ __forceinline__ float2 up2(u64t v) {
    float2 r;
    asm("mov.b64 {%0, %1}, %2;" : "=f"(r.x), "=f"(r.y) : "l"(v));
    return r;
}
__device__ __forceinline__ void fma2(u64t& d, u64t a, u64t b) {
#if __CUDA_ARCH__ >= 1000
    asm("fma.rn.f32x2 %0, %1, %2, %0;" : "+l"(d) : "l"(a), "l"(b));
#else
    float2 dd = up2(d), aa = up2(a), bb = up2(b);
    dd.x = fmaf(aa.x, bb.x, dd.x);
    dd.y = fmaf(aa.y, bb.y, dd.y);
    d = pk2(dd.x, dd.y);
#endif
}

__device__ __forceinline__ float gelu_exact(float v) {
    return 0.5f * v * (1.0f + erff(v * 0.70710678118654752f));
}

// ---------------- LayerNorm: one warp per token ----------------
__global__ __launch_bounds__(256) void ln_kernel(
    const float* __restrict__ x,
    const float* __restrict__ gamma,
    const float* __restrict__ beta,
    float* __restrict__ out)
{
    int lane = threadIdx.x & 31;
    int warp = threadIdx.x >> 5;
    int tok  = blockIdx.x * 8 + warp;

    const float4* px = (const float4*)(x + (size_t)tok * CDIM);
    float4 v0 = px[lane];
    float4 v1 = px[lane + 32];

    float s  = v0.x + v0.y + v0.z + v0.w + v1.x + v1.y + v1.z + v1.w;
    float ss = v0.x*v0.x + v0.y*v0.y + v0.z*v0.z + v0.w*v0.w
             + v1.x*v1.x + v1.y*v1.y + v1.z*v1.z + v1.w*v1.w;
    #pragma unroll
    for (int o = 16; o; o >>= 1) {
        s  += __shfl_xor_sync(0xffffffffu, s,  o);
        ss += __shfl_xor_sync(0xffffffffu, ss, o);
    }
    float mu  = s * (1.0f / 256.0f);
    float var = ss * (1.0f / 256.0f) - mu * mu;
    float rs  = rsqrtf(var + 1e-5f);

    const float4* pg = (const float4*)gamma;
    const float4* pb = (const float4*)beta;
    float4 g0 = pg[lane], g1 = pg[lane + 32];
    float4 b0 = pb[lane], b1 = pb[lane + 32];

    v0.x = (v0.x - mu) * rs * g0.x + b0.x;
    v0.y = (v0.y - mu) * rs * g0.y + b0.y;
    v0.z = (v0.z - mu) * rs * g0.z + b0.z;
    v0.w = (v0.w - mu) * rs * g0.w + b0.w;
    v1.x = (v1.x - mu) * rs * g1.x + b1.x;
    v1.y = (v1.y - mu) * rs * g1.y + b1.y;
    v1.z = (v1.z - mu) * rs * g1.z + b1.z;
    v1.w = (v1.w - mu) * rs * g1.w + b1.w;

    float4* po = (float4*)(out + (size_t)tok * CDIM);
    po[lane]      = v0;
    po[lane + 32] = v1;
}

// ---------------- tiled SGEMM 128x128x16, 8x8 microtile, zero-mov FFMA2 ----------------
// smem: A stored DUPLICATED ((a,a) pairs) -> a-operand pairs load as broadcast LDS.128
//       B stored natural                  -> b-operand pairs load straight from LDS.128
// EPI 0: out = gelu(acc + bias)
// EPI 1: out = res + acc + bias
// EPI 2: out = acc + bias
template<int EPI>
__global__ __launch_bounds__(256, 2) void gemm_kernel(
    const float* __restrict__ A,     // [M, K]
    const float* __restrict__ W,     // [K, N]
    const float* __restrict__ bias,  // [N]
    const float* __restrict__ res,   // [M, N] (EPI==1)
    float* __restrict__ out,         // [M, N]
    int M, int N, int K)
{
    __shared__ float As[16][264];    // duplicated: 2*128 + pad
    __shared__ float Bs[16][132];

    const int tid = threadIdx.x;
    const int tm  = tid >> 4;        // 0..15
    const int tn  = tid & 15;        // 0..15
    const int row0 = blockIdx.y * 128;
    const int col0 = blockIdx.x * 128;

    u64t acc[8][4] = {};             // 8 rows x 4 col-pairs

    const int arow = tid >> 2;            // 0..63
    const int ak4  = (tid & 3) << 2;      // 0,4,8,12
    const int bk   = tid >> 5;            // 0..7
    const int bc4  = (tid & 31) << 2;     // 0..124

    const float* Ap = A + (size_t)(row0 + arow) * K + ak4;
    const float* Wp = W + (size_t)bk * N + col0 + bc4;

    for (int kt = 0; kt < K; kt += 16) {
        float4 a0 = *(const float4*)(Ap + kt);
        float4 a1 = *(const float4*)(Ap + (size_t)64 * K + kt);
        float4 b0 = *(const float4*)(Wp + (size_t)kt * N);
        float4 b1 = *(const float4*)(Wp + (size_t)(kt + 8) * N);
        __syncthreads();
        {
            float av0[4] = {a0.x, a0.y, a0.z, a0.w};
            float av1[4] = {a1.x, a1.y, a1.z, a1.w};
            #pragma unroll
            for (int i = 0; i < 4; i++) {
                *(u64t*)&As[ak4 + i][2 * arow]       = pk2(av0[i], av0[i]);
                *(u64t*)&As[ak4 + i][128 + 2 * arow] = pk2(av1[i], av1[i]);
            }
        }
        *(float4*)&Bs[bk][bc4]     = b0;
        *(float4*)&Bs[bk + 8][bc4] = b1;
        __syncthreads();
        #pragma unroll
        for (int k = 0; k < 16; k++) {
            ulonglong2 bpa = *(const ulonglong2*)&Bs[k][tn * 4];
            ulonglong2 bpb = *(const ulonglong2*)&Bs[k][64 + tn * 4];
            ulonglong2 ad0 = *(const ulonglong2*)&As[k][tm * 8];
            ulonglong2 ad1 = *(const ulonglong2*)&As[k][tm * 8 + 4];
            ulonglong2 ad2 = *(const ulonglong2*)&As[k][128 + tm * 8];
            ulonglong2 ad3 = *(const ulonglong2*)&As[k][128 + tm * 8 + 4];
            u64t ad[8] = {ad0.x, ad0.y, ad1.x, ad1.y, ad2.x, ad2.y, ad3.x, ad3.y};
            u64t bp[4] = {bpa.x, bpa.y, bpb.x, bpb.y};
            #pragma unroll
            for (int r = 0; r < 8; r++) {
                #pragma unroll
                for (int cp = 0; cp < 4; cp++)
                    fma2(acc[r][cp], ad[r], bp[cp]);
            }
        }
    }

    // epilogue
    #pragma unroll
    for (int r = 0; r < 8; r++) {
        int row = row0 + ((r < 4) ? (tm * 4 + r) : (64 + tm * 4 + r - 4));
        #pragma unroll
        for (int half = 0; half < 2; half++) {
            int cb = col0 + half * 64 + tn * 4;
            float2 t0 = up2(acc[r][half * 2]);
            float2 t1 = up2(acc[r][half * 2 + 1]);
            float vals[4] = {t0.x, t0.y, t1.x, t1.y};
            const float4 bv = *(const float4*)(bias + cb);
            vals[0] += bv.x; vals[1] += bv.y; vals[2] += bv.z; vals[3] += bv.w;
            if (EPI == 0) {
                #pragma unroll
                for (int l = 0; l < 4; l++) vals[l] = gelu_exact(vals[l]);
            } else if (EPI == 1) {
                const float4 rv = *(const float4*)(res + (size_t)row * N + cb);
                vals[0] += rv.x; vals[1] += rv.y; vals[2] += rv.z; vals[3] += rv.w;
            }
            *(float4*)(out + (size_t)row * N + cb) =
                make_float4(vals[0], vals[1], vals[2], vals[3]);
        }
    }
}

// ---------------- attention core: one CTA per window, one warp per head ----------------
// q read from gmem per row; k (pad 36, float4) and v (pad 33) staged in smem.
// probabilities kept in registers, broadcast via shfl for the AV pass.
#define KPAD 36
#define VPAD 33
#define SM_KH   0
#define SM_VH   (NHEAD*SWIN*KPAD)                     // 14112
#define SM_AINT (SM_VH + NHEAD*SWIN*VPAD)             // +12936
#define ATT_SMEM ((SM_AINT + 2*SWIN) * 4)

__global__ __launch_bounds__(256) void attn_kernel(
    const float* __restrict__ qkv,    // [NTOK, 768] (q|k|v)
    const float* __restrict__ btab,   // [169, 8]
    float* __restrict__ o_out)        // [NTOK, 256]
{
    extern __shared__ float sm[];
    float* kh  = sm + SM_KH;
    float* vh  = sm + SM_VH;
    int* tsrc  = (int*)(sm + SM_AINT);
    int* regid = tsrc + SWIN;

    const int tid  = threadIdx.x;
    const int lane = tid & 31;
    const int h    = tid >> 5;        // head = warp

    const int win = blockIdx.x;
    const int b   = win >> 6;
    const int wq  = win & 63;
    const int wy  = wq >> 3;
    const int wx  = wq & 7;

    if (tid < SWIN) {
        int i = tid / 7, j = tid - i * 7;
        int y  = wy * 7 + i;
        int xx = wx * 7 + j;
        int y0 = y  + SHIFTS; if (y0 >= IMG) y0 -= IMG;
        int x0 = xx + SHIFTS; if (x0 >= IMG) x0 -= IMG;
        tsrc[tid] = b * (IMG * IMG) + y0 * IMG + x0;
        // faithful mask regions (the empty (-7,-7) w-slice leaves cols 49..52 at 0)
        int rc = (y <= 48) ? 0 : ((y <= 52) ? 1 : 2);
        regid[tid] = (xx <= 48) ? rc * 3 : ((xx >= 53) ? rc * 3 + 2 : 0);
    }
    __syncthreads();

    // stage this head's k and v
    float* kw = kh + h * (SWIN * KPAD);
    float* vw = vh + h * (SWIN * VPAD);
    {
        const int hc = h * 32 + lane;
        for (int s = 0; s < SWIN; s++) {
            size_t g = (size_t)tsrc[s] * (3 * CDIM);
            kw[s * KPAD + lane] = qkv[g + CDIM     + hc];
            vw[s * VPAD + lane] = qkv[g + 2 * CDIM + hc];
        }
    }
    __syncwarp();

    const int t1  = lane;
    const int t2  = lane + 32;
    const bool v2 = (t2 < SWIN);
    const int t2c = v2 ? t2 : 48;
    const int it1 = t1 / 7,  jt1 = t1 - it1 * 7;
    const int it2 = t2c / 7, jt2 = t2c - it2 * 7;
    const int r1  = regid[t1];
    const int r2  = regid[t2c];

    for (int s = 0; s < SWIN; s++) {
        // q row (lane = d), direct from gmem
        float qd = qkv[(size_t)tsrc[s] * (3 * CDIM) + h * 32 + lane] * QSCALE;

        float a1 = 0.f, a2 = 0.f;
        #pragma unroll
        for (int d4 = 0; d4 < 8; d4++) {
            float4 k1 = *(const float4*)&kw[t1  * KPAD + d4 * 4];
            float4 k2 = *(const float4*)&kw[t2c * KPAD + d4 * 4];
            float q0 = __shfl_sync(0xffffffffu, qd, d4 * 4 + 0);
            float q1 = __shfl_sync(0xffffffffu, qd, d4 * 4 + 1);
            float q2 = __shfl_sync(0xffffffffu, qd, d4 * 4 + 2);
            float q3 = __shfl_sync(0xffffffffu, qd, d4 * 4 + 3);
            a1 = fmaf(q0, k1.x, a1); a1 = fmaf(q1, k1.y, a1);
            a1 = fmaf(q2, k1.z, a1); a1 = fmaf(q3, k1.w, a1);
            a2 = fmaf(q0, k2.x, a2); a2 = fmaf(q1, k2.y, a2);
            a2 = fmaf(q2, k2.z, a2); a2 = fmaf(q3, k2.w, a2);
        }

        int i1 = s / 7, j1 = s - i1 * 7;
        int rs = regid[s];
        {
            int ridx = (i1 - it1 + 6) * 13 + (j1 - jt1 + 6);
            a1 += btab[ridx * NHEAD + h];
            if (rs != r1) a1 -= 100.0f;
        }
        if (v2) {
            int ridx = (i1 - it2 + 6) * 13 + (j1 - jt2 + 6);
            a2 += btab[ridx * NHEAD + h];
            if (rs != r2) a2 -= 100.0f;
        } else {
            a2 = -1e30f;
        }

        // softmax over 49
        float m = fmaxf(a1, a2);
        #pragma unroll
        for (int o = 16; o; o >>= 1) m = fmaxf(m, __shfl_xor_sync(0xffffffffu, m, o));
        float e1 = __expf(a1 - m);
        float e2 = v2 ? __expf(a2 - m) : 0.0f;
        float sum = e1 + e2;
        #pragma unroll
        for (int o = 16; o; o >>= 1) sum += __shfl_xor_sync(0xffffffffu, sum, o);
        float inv = 1.0f / sum;
        float p1 = e1 * inv;     // att[s][lane]
        float p2 = e2 * inv;     // att[s][lane+32]

        // o[s][lane] = sum_t att[s][t] * v[t][lane]
        float oa = 0.f;
        #pragma unroll
        for (int t = 0; t < 32; t++) {
            float av = __shfl_sync(0xffffffffu, p1, t);
            oa = fmaf(av, vw[t * VPAD + lane], oa);
        }
        #pragma unroll
        for (int t = 32; t < SWIN; t++) {
            float av = __shfl_sync(0xffffffffu, p2, t - 32);
            oa = fmaf(av, vw[t * VPAD + lane], oa);
        }
        o_out[(size_t)tsrc[s] * CDIM + h * 32 + lane] = oa;
    }
}

// ---------------- launch ----------------
extern "C" void kernel_launch(void* const* d_in, const int* in_sizes, int n_in,
                              void* d_out, int out_size)
{
    const float* x      = (const float*)d_in[0];
    const float* gamma  = (const float*)d_in[1];
    const float* beta   = (const float*)d_in[2];
    const float* qkv_w  = (const float*)d_in[3];
    const float* qkv_b  = (const float*)d_in[4];
    const float* proj_w = (const float*)d_in[5];
    const float* proj_b = (const float*)d_in[6];
    const float* btab   = (const float*)d_in[7];
    const float* w1     = (const float*)d_in[8];
    const float* b1     = (const float*)d_in[9];
    const float* w2     = (const float*)d_in[10];
    const float* b2     = (const float*)d_in[11];
    float* out = (float*)d_out;

    float *xn, *x1, *qkv, *xn2, *hbuf;
    cudaGetSymbolAddress((void**)&xn,   g_xn);
    cudaGetSymbolAddress((void**)&x1,   g_x1);
    cudaGetSymbolAddress((void**)&qkv,  g_qkv);
    cudaGetSymbolAddress((void**)&xn2,  g_xn2);
    cudaGetSymbolAddress((void**)&hbuf, g_h);

    cudaFuncSetAttribute(attn_kernel,
                         cudaFuncAttributeMaxDynamicSharedMemorySize, ATT_SMEM);

    // 1) xn = LN(x)
    ln_kernel<<<NTOK / 8, 256>>>(x, gamma, beta, xn);
    // 2) qkv = xn @ qkv_w + qkv_b          [NTOK, 768]
    gemm_kernel<2><<<dim3(3 * CDIM / 128, NTOK / 128), 256>>>(
        xn, qkv_w, qkv_b, nullptr, qkv, NTOK, 3 * CDIM, CDIM);
    // 3) o = windowed attention(qkv)       -> reuse g_xn
    attn_kernel<<<BATCH * NWIN, 256, ATT_SMEM>>>(qkv, btab, xn);
    // 4) x1 = x + o @ proj_w + proj_b
    gemm_kernel<1><<<dim3(CDIM / 128, NTOK / 128), 256>>>(
        xn, proj_w, proj_b, x, x1, NTOK, CDIM, CDIM);
    // 5) xn2 = LN(x1)
    ln_kernel<<<NTOK / 8, 256>>>(x1, gamma, beta, xn2);
    // 6) h = gelu(xn2 @ w1 + b1)
    gemm_kernel<0><<<dim3(NMLP / 128, NTOK / 128), 256>>>(
        xn2, w1, b1, nullptr, hbuf, NTOK, NMLP, CDIM);
    // 7) out = x1 + h @ w2 + b2
    gemm_kernel<1><<<dim3(CDIM / 128, NTOK / 128), 256>>>(
        hbuf, w2, b2, x1, out, NTOK, CDIM, NMLP);
}

// round 6
// speedup vs baseline: 1.8068x; 1.5831x over previous
#include <cuda_runtime.h>
#include <cuda_bf16.h>
#include <cstdint>
#include <cstddef>

// ---------------- static problem config ----------------
#define IMG    56
#define WIN    7
#define SHIFTS 3
#define CDIM   256
#define NHEAD  8
#define DHEAD  32
#define SWIN   49
#define NWIN   64
#define NMLP   1024
#define BATCH  32
#define NTOK   (BATCH*IMG*IMG)           // 100352
#define QSCALE 0.17677669529663689f

// ---------------- scratch (device globals) ----------------
__device__ __nv_bfloat16 g_xnb [(size_t)NTOK * 2 * CDIM];   // LN1 out, hi|lo
__device__ __nv_bfloat16 g_ob  [(size_t)NTOK * 2 * CDIM];   // attn out, hi|lo
__device__ __nv_bfloat16 g_xn2b[(size_t)NTOK * 2 * CDIM];   // LN2 out, hi|lo
__device__ __nv_bfloat16 g_hb  [(size_t)NTOK * 2 * NMLP];   // gelu out, hi|lo
__device__ float         g_qkv [(size_t)NTOK * 3 * CDIM];   // qkv fp32
__device__ float         g_x1  [(size_t)NTOK * CDIM];       // x + attn
__device__ __nv_bfloat16 g_wq  [(size_t)(3*CDIM) * 2 * CDIM];
__device__ __nv_bfloat16 g_wp  [(size_t)CDIM * 2 * CDIM];
__device__ __nv_bfloat16 g_w1b [(size_t)NMLP * 2 * CDIM];
__device__ __nv_bfloat16 g_w2b [(size_t)CDIM * 2 * NMLP];

// ---------------- helpers ----------------
__device__ __forceinline__ float gelu_exact(float v) {
    return 0.5f * v * (1.0f + erff(v * 0.70710678118654752f));
}
__device__ __forceinline__ void bsplit(float v, __nv_bfloat16& hi, __nv_bfloat16& lo) {
    hi = __float2bfloat16(v);
    lo = __float2bfloat16(v - __bfloat162float(hi));
}
__device__ __forceinline__ uint32_t smem_u32(const void* p) {
    uint32_t a;
    asm("{ .reg .u64 t; cvta.to.shared.u64 t, %1; cvt.u32.u64 %0, t; }"
        : "=r"(a) : "l"(p));
    return a;
}
__device__ __forceinline__ void ldsm4(uint32_t* r, uint32_t addr) {
    asm volatile("ldmatrix.sync.aligned.m8n8.x4.shared.b16 {%0,%1,%2,%3}, [%4];"
        : "=r"(r[0]), "=r"(r[1]), "=r"(r[2]), "=r"(r[3]) : "r"(addr));
}
__device__ __forceinline__ void mma16816(float* c, const uint32_t* a,
                                         uint32_t b0, uint32_t b1) {
    asm volatile("mma.sync.aligned.m16n8k16.row.col.f32.bf16.bf16.f32 "
        "{%0,%1,%2,%3}, {%4,%5,%6,%7}, {%8,%9}, {%0,%1,%2,%3};"
        : "+f"(c[0]), "+f"(c[1]), "+f"(c[2]), "+f"(c[3])
        : "r"(a[0]), "r"(a[1]), "r"(a[2]), "r"(a[3]), "r"(b0), "r"(b1));
}
__device__ __forceinline__ void cpa16(uint32_t s, const void* g) {
    asm volatile("cp.async.cg.shared.global [%0], [%1], 16;" :: "r"(s), "l"(g));
}
#define CP_COMMIT() asm volatile("cp.async.commit_group;" ::: "memory")
#define CP_WAIT1()  asm volatile("cp.async.wait_group 1;" ::: "memory")
#define CP_WAIT0()  asm volatile("cp.async.wait_group 0;" ::: "memory")

// ---------------- weight prep: W [K,N] fp32 -> Wb [N, 2K] bf16 (hi|lo) ----------------
__global__ void wprep(const float* __restrict__ W, __nv_bfloat16* __restrict__ Wb,
                      int K, int N)
{
    int idx = blockIdx.x * 256 + threadIdx.x;
    if (idx >= K * N) return;
    int k = idx / N, n = idx - k * N;
    __nv_bfloat16 hi, lo;
    bsplit(W[idx], hi, lo);
    Wb[(size_t)n * 2 * K + k]     = hi;
    Wb[(size_t)n * 2 * K + K + k] = lo;
}

// ---------------- LayerNorm -> bf16 split ----------------
__global__ __launch_bounds__(256) void ln_split_kernel(
    const float* __restrict__ x,
    const float* __restrict__ gamma,
    const float* __restrict__ beta,
    __nv_bfloat16* __restrict__ outb)   // [NTOK, 512] hi|lo
{
    int lane = threadIdx.x & 31;
    int warp = threadIdx.x >> 5;
    int tok  = blockIdx.x * 8 + warp;

    const float4* px = (const float4*)(x + (size_t)tok * CDIM);
    float4 v0 = px[lane];
    float4 v1 = px[lane + 32];

    float s  = v0.x + v0.y + v0.z + v0.w + v1.x + v1.y + v1.z + v1.w;
    float ss = v0.x*v0.x + v0.y*v0.y + v0.z*v0.z + v0.w*v0.w
             + v1.x*v1.x + v1.y*v1.y + v1.z*v1.z + v1.w*v1.w;
    #pragma unroll
    for (int o = 16; o; o >>= 1) {
        s  += __shfl_xor_sync(0xffffffffu, s,  o);
        ss += __shfl_xor_sync(0xffffffffu, ss, o);
    }
    float mu  = s * (1.0f / 256.0f);
    float var = ss * (1.0f / 256.0f) - mu * mu;
    float rs  = rsqrtf(var + 1e-5f);

    const float4* pg = (const float4*)gamma;
    const float4* pb = (const float4*)beta;
    float4 g0 = pg[lane], g1 = pg[lane + 32];
    float4 b0 = pb[lane], b1 = pb[lane + 32];

    float r0[4] = { (v0.x-mu)*rs*g0.x+b0.x, (v0.y-mu)*rs*g0.y+b0.y,
                    (v0.z-mu)*rs*g0.z+b0.z, (v0.w-mu)*rs*g0.w+b0.w };
    float r1[4] = { (v1.x-mu)*rs*g1.x+b1.x, (v1.y-mu)*rs*g1.y+b1.y,
                    (v1.z-mu)*rs*g1.z+b1.z, (v1.w-mu)*rs*g1.w+b1.w };

    __nv_bfloat16* base = outb + (size_t)tok * (2 * CDIM);
    #pragma unroll
    for (int g = 0; g < 2; g++) {
        float* rv = g ? r1 : r0;
        int c = g * 128 + lane * 4;
        __nv_bfloat162 h01, h23, l01, l23;
        bsplit(rv[0], h01.x, l01.x); bsplit(rv[1], h01.y, l01.y);
        bsplit(rv[2], h23.x, l23.x); bsplit(rv[3], h23.y, l23.y);
        *(__nv_bfloat162*)(base + c)            = h01;
        *(__nv_bfloat162*)(base + c + 2)        = h23;
        *(__nv_bfloat162*)(base + CDIM + c)     = l01;
        *(__nv_bfloat162*)(base + CDIM + c + 2) = l23;
    }
}

// ---------------- HMMA GEMM: 128x128 tile, bf16 3-term split ----------------
// A [M, 2K] bf16 (hi|lo), Bw [N, 2K] bf16 (hi|lo). acc = Ahi*Bhi + Alo*Bhi + Ahi*Blo.
// EPI 0: outb = split(gelu(acc + bias)); EPI 1: outf = res + acc + bias; EPI 2: outf = acc + bias
template<int EPI>
__global__ __launch_bounds__(256, 2) void hgemm(
    const __nv_bfloat16* __restrict__ A,
    const __nv_bfloat16* __restrict__ Bw,
    const float* __restrict__ bias,
    const float* __restrict__ res,
    float* __restrict__ outf,
    __nv_bfloat16* __restrict__ outb,
    int M, int N, int K)
{
    __shared__ __nv_bfloat16 sA[2][128 * 32];
    __shared__ __nv_bfloat16 sB[2][128 * 32];

    const int tid  = threadIdx.x;
    const int lane = tid & 31;
    const int wid  = tid >> 5;
    const int wm   = wid >> 1;       // 0..3
    const int wn   = wid & 1;        // 0..1
    const int row0 = blockIdx.y * 128;
    const int col0 = blockIdx.x * 128;
    const size_t ld2k = 2 * (size_t)K;
    const int nk  = K / 32;
    const int nch = 3 * nk;

    const uint32_t sAb = smem_u32(sA);
    const uint32_t sBb = smem_u32(sB);

    // fill mapping: thread -> (row fr, k-granules fk0, fk0+1)
    const int fr  = tid >> 1;            // 0..127
    const int fk0 = (tid & 1) * 2;       // 0 or 2
    uint32_t stO[2];
    #pragma unroll
    for (int i = 0; i < 2; i++) {
        int kg = fk0 + i;
        int sg = kg ^ ((fr >> 1) & 3);
        stO[i] = (uint32_t)((fr * 32 + sg * 8) * 2);
    }
    const __nv_bfloat16* Afr = A  + (size_t)(row0 + fr) * ld2k;
    const __nv_bfloat16* Bfr = Bw + (size_t)(col0 + fr) * ld2k;

    float acc[2][8][4];
    #pragma unroll
    for (int a = 0; a < 2; a++)
        #pragma unroll
        for (int b = 0; b < 8; b++)
            #pragma unroll
            for (int c = 0; c < 4; c++) acc[a][b][c] = 0.f;

    // issue chunk g into buffer buf
    auto issue = [&](int g, int buf) {
        int p = g / nk, c = g - p * nk;
        int ao = ((p == 1) ? K : 0) + c * 32 + fk0 * 8;
        int bo = ((p == 2) ? K : 0) + c * 32 + fk0 * 8;
        uint32_t sa = sAb + buf * 8192;
        uint32_t sb = sBb + buf * 8192;
        #pragma unroll
        for (int i = 0; i < 2; i++) {
            cpa16(sa + stO[i], Afr + ao + i * 8);
            cpa16(sb + stO[i], Bfr + bo + i * 8);
        }
        CP_COMMIT();
    };

    issue(0, 0);
    for (int g = 0; g < nch; g++) {
        if (g + 1 < nch) { issue(g + 1, (g + 1) & 1); CP_WAIT1(); }
        else             { CP_WAIT0(); }
        __syncthreads();

        const uint32_t aB = sAb + (g & 1) * 8192;
        const uint32_t bB = sBb + (g & 1) * 8192;
        #pragma unroll
        for (int kt = 0; kt < 2; kt++) {
            uint32_t a[2][4], b[4][4];
            const int kg = kt * 2 + (lane >> 4);
            #pragma unroll
            for (int mt = 0; mt < 2; mt++) {
                int r  = wm * 32 + mt * 16 + (lane & 15);
                int sg = kg ^ ((r >> 1) & 3);
                ldsm4(a[mt], aB + (uint32_t)((r * 32 + sg * 8) * 2));
            }
            #pragma unroll
            for (int nb = 0; nb < 4; nb++) {
                int r  = wn * 64 + nb * 16 + (lane & 15);
                int sg = kg ^ ((r >> 1) & 3);
                ldsm4(b[nb], bB + (uint32_t)((r * 32 + sg * 8) * 2));
            }
            #pragma unroll
            for (int mt = 0; mt < 2; mt++)
                #pragma unroll
                for (int nb = 0; nb < 4; nb++) {
                    mma16816(acc[mt][2 * nb],     a[mt], b[nb][0], b[nb][2]);
                    mma16816(acc[mt][2 * nb + 1], a[mt], b[nb][1], b[nb][3]);
                }
        }
        __syncthreads();
    }

    // epilogue
    const int g4 = lane >> 2, q = lane & 3;
    #pragma unroll
    for (int mt = 0; mt < 2; mt++) {
        #pragma unroll
        for (int half = 0; half < 2; half++) {
            int row = row0 + wm * 32 + mt * 16 + g4 + half * 8;
            #pragma unroll
            for (int nt = 0; nt < 8; nt++) {
                int col = col0 + wn * 64 + nt * 8 + q * 2;
                float v0 = acc[mt][nt][half * 2 + 0] + bias[col];
                float v1 = acc[mt][nt][half * 2 + 1] + bias[col + 1];
                if (EPI == 2) {
                    *(float2*)(outf + (size_t)row * N + col) = make_float2(v0, v1);
                } else if (EPI == 1) {
                    const float2 rv = *(const float2*)(res + (size_t)row * N + col);
                    *(float2*)(outf + (size_t)row * N + col) =
                        make_float2(v0 + rv.x, v1 + rv.y);
                } else {
                    v0 = gelu_exact(v0);
                    v1 = gelu_exact(v1);
                    __nv_bfloat162 hp, lp;
                    bsplit(v0, hp.x, lp.x);
                    bsplit(v1, hp.y, lp.y);
                    __nv_bfloat16* hr = outb + (size_t)row * 2 * N + col;
                    *(__nv_bfloat162*)hr       = hp;
                    *(__nv_bfloat162*)(hr + N) = lp;
                }
            }
        }
    }
}

// ---------------- attention: one CTA per window, one warp per head ----------------
#define KPAD 36
#define VPAD 33
#define SM_KH   0
#define SM_VH   (NHEAD*SWIN*KPAD)
#define SM_AINT (SM_VH + NHEAD*SWIN*VPAD)
#define ATT_SMEM ((SM_AINT + 2*SWIN) * 4)

__global__ __launch_bounds__(256) void attn_kernel(
    const float* __restrict__ qkv,    // [NTOK, 768] (q|k|v)
    const float* __restrict__ btab,   // [169, 8]
    __nv_bfloat16* __restrict__ o_bf) // [NTOK, 512] hi|lo
{
    extern __shared__ float sm[];
    float* kh  = sm + SM_KH;
    float* vh  = sm + SM_VH;
    int* tsrc  = (int*)(sm + SM_AINT);
    int* regid = tsrc + SWIN;

    const int tid  = threadIdx.x;
    const int lane = tid & 31;
    const int h    = tid >> 5;

    const int win = blockIdx.x;
    const int b   = win >> 6;
    const int wq  = win & 63;
    const int wy  = wq >> 3;
    const int wx  = wq & 7;

    if (tid < SWIN) {
        int i = tid / 7, j = tid - i * 7;
        int y  = wy * 7 + i;
        int xx = wx * 7 + j;
        int y0 = y  + SHIFTS; if (y0 >= IMG) y0 -= IMG;
        int x0 = xx + SHIFTS; if (x0 >= IMG) x0 -= IMG;
        tsrc[tid] = b * (IMG * IMG) + y0 * IMG + x0;
        int rc = (y <= 48) ? 0 : ((y <= 52) ? 1 : 2);
        regid[tid] = (xx <= 48) ? rc * 3 : ((xx >= 53) ? rc * 3 + 2 : 0);
    }
    __syncthreads();

    float* kw = kh + h * (SWIN * KPAD);
    float* vw = vh + h * (SWIN * VPAD);
    {
        const int hc = h * 32 + lane;
        for (int s = 0; s < SWIN; s++) {
            size_t g = (size_t)tsrc[s] * (3 * CDIM);
            kw[s * KPAD + lane] = qkv[g + CDIM     + hc];
            vw[s * VPAD + lane] = qkv[g + 2 * CDIM + hc];
        }
    }
    __syncwarp();

    const int t1  = lane;
    const int t2  = lane + 32;
    const bool v2 = (t2 < SWIN);
    const int t2c = v2 ? t2 : 48;
    const int it1 = t1 / 7,  jt1 = t1 - it1 * 7;
    const int it2 = t2c / 7, jt2 = t2c - it2 * 7;
    const int r1  = regid[t1];
    const int r2  = regid[t2c];

    for (int s = 0; s < SWIN; s++) {
        float qd = qkv[(size_t)tsrc[s] * (3 * CDIM) + h * 32 + lane] * QSCALE;

        float a1 = 0.f, a2 = 0.f;
        #pragma unroll
        for (int d4 = 0; d4 < 8; d4++) {
            float4 k1 = *(const float4*)&kw[t1  * KPAD + d4 * 4];
            float4 k2 = *(const float4*)&kw[t2c * KPAD + d4 * 4];
            float q0 = __shfl_sync(0xffffffffu, qd, d4 * 4 + 0);
            float q1 = __shfl_sync(0xffffffffu, qd, d4 * 4 + 1);
            float q2 = __shfl_sync(0xffffffffu, qd, d4 * 4 + 2);
            float q3 = __shfl_sync(0xffffffffu, qd, d4 * 4 + 3);
            a1 = fmaf(q0, k1.x, a1); a1 = fmaf(q1, k1.y, a1);
            a1 = fmaf(q2, k1.z, a1); a1 = fmaf(q3, k1.w, a1);
            a2 = fmaf(q0, k2.x, a2); a2 = fmaf(q1, k2.y, a2);
            a2 = fmaf(q2, k2.z, a2); a2 = fmaf(q3, k2.w, a2);
        }

        int i1 = s / 7, j1 = s - i1 * 7;
        int rs = regid[s];
        {
            int ridx = (i1 - it1 + 6) * 13 + (j1 - jt1 + 6);
            a1 += btab[ridx * NHEAD + h];
            if (rs != r1) a1 -= 100.0f;
        }
        if (v2) {
            int ridx = (i1 - it2 + 6) * 13 + (j1 - jt2 + 6);
            a2 += btab[ridx * NHEAD + h];
            if (rs != r2) a2 -= 100.0f;
        } else {
            a2 = -1e30f;
        }

        float m = fmaxf(a1, a2);
        #pragma unroll
        for (int o = 16; o; o >>= 1) m = fmaxf(m, __shfl_xor_sync(0xffffffffu, m, o));
        float e1 = __expf(a1 - m);
        float e2 = v2 ? __expf(a2 - m) : 0.0f;
        float sum = e1 + e2;
        #pragma unroll
        for (int o = 16; o; o >>= 1) sum += __shfl_xor_sync(0xffffffffu, sum, o);
        float inv = 1.0f / sum;
        float p1 = e1 * inv;
        float p2 = e2 * inv;

        float oa = 0.f;
        #pragma unroll
        for (int t = 0; t < 32; t++) {
            float av = __shfl_sync(0xffffffffu, p1, t);
            oa = fmaf(av, vw[t * VPAD + lane], oa);
        }
        #pragma unroll
        for (int t = 32; t < SWIN; t++) {
            float av = __shfl_sync(0xffffffffu, p2, t - 32);
            oa = fmaf(av, vw[t * VPAD + lane], oa);
        }
        __nv_bfloat16 hi, lo;
        bsplit(oa, hi, lo);
        size_t ob = (size_t)tsrc[s] * (2 * CDIM) + h * 32 + lane;
        o_bf[ob]        = hi;
        o_bf[ob + CDIM] = lo;
    }
}

// ---------------- launch ----------------
extern "C" void kernel_launch(void* const* d_in, const int* in_sizes, int n_in,
                              void* d_out, int out_size)
{
    const float* x      = (const float*)d_in[0];
    const float* gamma  = (const float*)d_in[1];
    const float* beta   = (const float*)d_in[2];
    const float* qkv_w  = (const float*)d_in[3];
    const float* qkv_b  = (const float*)d_in[4];
    const float* proj_w = (const float*)d_in[5];
    const float* proj_b = (const float*)d_in[6];
    const float* btab   = (const float*)d_in[7];
    const float* w1     = (const float*)d_in[8];
    const float* b1     = (const float*)d_in[9];
    const float* w2     = (const float*)d_in[10];
    const float* b2     = (const float*)d_in[11];
    float* out = (float*)d_out;

    __nv_bfloat16 *xnb, *ob, *xn2b, *hb, *wq, *wp, *w1b, *w2b;
    float *qkv, *x1;
    cudaGetSymbolAddress((void**)&xnb,  g_xnb);
    cudaGetSymbolAddress((void**)&ob,   g_ob);
    cudaGetSymbolAddress((void**)&xn2b, g_xn2b);
    cudaGetSymbolAddress((void**)&hb,   g_hb);
    cudaGetSymbolAddress((void**)&wq,   g_wq);
    cudaGetSymbolAddress((void**)&wp,   g_wp);
    cudaGetSymbolAddress((void**)&w1b,  g_w1b);
    cudaGetSymbolAddress((void**)&w2b,  g_w2b);
    cudaGetSymbolAddress((void**)&qkv,  g_qkv);
    cudaGetSymbolAddress((void**)&x1,   g_x1);

    cudaFuncSetAttribute(attn_kernel, cudaFuncAttributeMaxDynamicSharedMemorySize, ATT_SMEM);

    // weight prep (bf16 split + transpose)
    wprep<<<(CDIM * 3 * CDIM + 255) / 256, 256>>>(qkv_w,  wq,  CDIM, 3 * CDIM);
    wprep<<<(CDIM * CDIM     + 255) / 256, 256>>>(proj_w, wp,  CDIM, CDIM);
    wprep<<<(CDIM * NMLP     + 255) / 256, 256>>>(w1,     w1b, CDIM, NMLP);
    wprep<<<(NMLP * CDIM     + 255) / 256, 256>>>(w2,     w2b, NMLP, CDIM);

    // 1) LN1(x) -> bf16 split
    ln_split_kernel<<<NTOK / 8, 256>>>(x, gamma, beta, xnb);
    // 2) qkv = xn @ qkv_w + qkv_b   (fp32 out)
    hgemm<2><<<dim3(3 * CDIM / 128, NTOK / 128), 256>>>(
        xnb, wq, qkv_b, nullptr, qkv, nullptr, NTOK, 3 * CDIM, CDIM);
    // 3) windowed attention -> bf16 split
    attn_kernel<<<BATCH * NWIN, 256, ATT_SMEM>>>(qkv, btab, ob);
    // 4) x1 = x + o @ proj_w + proj_b
    hgemm<1><<<dim3(CDIM / 128, NTOK / 128), 256>>>(
        ob, wp, proj_b, x, x1, nullptr, NTOK, CDIM, CDIM);
    // 5) LN2(x1) -> bf16 split
    ln_split_kernel<<<NTOK / 8, 256>>>(x1, gamma, beta, xn2b);
    // 6) h = gelu(xn2 @ w1 + b1) -> bf16 split
    hgemm<0><<<dim3(NMLP / 128, NTOK / 128), 256>>>(
        xn2b, w1b, b1, nullptr, nullptr, hb, NTOK, NMLP, CDIM);
    // 7) out = x1 + h @ w2 + b2
    hgemm<1><<<dim3(CDIM / 128, NTOK / 128), 256>>>(
        hb, w2b, b2, x1, out, nullptr, NTOK, CDIM, NMLP);
}

// round 8
// speedup vs baseline: 2.7116x; 1.5007x over previous
#include <cuda_runtime.h>
#include <cuda_fp16.h>
#include <cstdint>
#include <cstddef>

// ---------------- static problem config ----------------
#define IMG    56
#define WIN    7
#define SHIFTS 3
#define CDIM   256
#define NHEAD  8
#define DHEAD  32
#define SWIN   49
#define NWIN   64
#define NMLP   1024
#define BATCH  32
#define NTOK   (BATCH*IMG*IMG)           // 100352
#define QSCALE 0.17677669529663689f

// ---------------- scratch (device globals) ----------------
__device__ __half g_xnh [(size_t)NTOK * 2 * CDIM];   // LN1 out, hi|lo fp16
__device__ __half g_oh  [(size_t)NTOK * 2 * CDIM];   // attn out, hi|lo
__device__ __half g_xn2h[(size_t)NTOK * 2 * CDIM];   // LN2 out, hi|lo
__device__ __half g_hh  [(size_t)NTOK * 2 * NMLP];   // gelu out, hi|lo
__device__ float  g_qkv [(size_t)NTOK * 3 * CDIM];   // qkv fp32
__device__ float  g_x1  [(size_t)NTOK * CDIM];       // x + attn
__device__ __half g_wq  [(size_t)(3*CDIM) * CDIM];   // weights [N,K] fp16
__device__ __half g_wp  [(size_t)CDIM * CDIM];
__device__ __half g_w1h [(size_t)NMLP * CDIM];
__device__ __half g_w2h [(size_t)CDIM * NMLP];

// ---------------- helpers ----------------
__device__ __forceinline__ float gelu_exact(float v) {
    return 0.5f * v * (1.0f + erff(v * 0.70710678118654752f));
}
__device__ __forceinline__ void hsplit(float v, __half& hi, __half& lo) {
    hi = __float2half_rn(v);
    lo = __float2half_rn(v - __half2float(hi));
}
__device__ __forceinline__ uint32_t smem_u32(const void* p) {
    uint32_t a;
    asm("{ .reg .u64 t; cvta.to.shared.u64 t, %1; cvt.u32.u64 %0, t; }"
        : "=r"(a) : "l"(p));
    return a;
}
__device__ __forceinline__ void ldsm4(uint32_t* r, uint32_t addr) {
    asm volatile("ldmatrix.sync.aligned.m8n8.x4.shared.b16 {%0,%1,%2,%3}, [%4];"
        : "=r"(r[0]), "=r"(r[1]), "=r"(r[2]), "=r"(r[3]) : "r"(addr));
}
__device__ __forceinline__ void mma16816(float* c, const uint32_t* a,
                                         uint32_t b0, uint32_t b1) {
    asm volatile("mma.sync.aligned.m16n8k16.row.col.f32.f16.f16.f32 "
        "{%0,%1,%2,%3}, {%4,%5,%6,%7}, {%8,%9}, {%0,%1,%2,%3};"
        : "+f"(c[0]), "+f"(c[1]), "+f"(c[2]), "+f"(c[3])
        : "r"(a[0]), "r"(a[1]), "r"(a[2]), "r"(a[3]), "r"(b0), "r"(b1));
}
__device__ __forceinline__ void cpa16(uint32_t s, const void* g) {
    asm volatile("cp.async.cg.shared.global [%0], [%1], 16;" :: "r"(s), "l"(g));
}
#define CP_COMMIT() asm volatile("cp.async.commit_group;" ::: "memory")
#define CP_WAIT1()  asm volatile("cp.async.wait_group 1;" ::: "memory")
#define CP_WAIT0()  asm volatile("cp.async.wait_group 0;" ::: "memory")

// ---------------- weight prep: W [K,N] fp32 -> Wh [N,K] fp16 ----------------
__global__ void wprep_t(const float* __restrict__ W, __half* __restrict__ Wh,
                        int K, int N)
{
    int idx = blockIdx.x * 256 + threadIdx.x;
    if (idx >= K * N) return;
    int k = idx / N, n = idx - k * N;
    Wh[(size_t)n * K + k] = __float2half_rn(W[idx]);
}

// ---------------- LayerNorm -> fp16 hi|lo split ----------------
__global__ __launch_bounds__(256) void ln_split_kernel(
    const float* __restrict__ x,
    const float* __restrict__ gamma,
    const float* __restrict__ beta,
    __half* __restrict__ outh)   // [NTOK, 512] hi|lo
{
    int lane = threadIdx.x & 31;
    int warp = threadIdx.x >> 5;
    int tok  = blockIdx.x * 8 + warp;

    const float4* px = (const float4*)(x + (size_t)tok * CDIM);
    float4 v0 = px[lane];
    float4 v1 = px[lane + 32];

    float s  = v0.x + v0.y + v0.z + v0.w + v1.x + v1.y + v1.z + v1.w;
    float ss = v0.x*v0.x + v0.y*v0.y + v0.z*v0.z + v0.w*v0.w
             + v1.x*v1.x + v1.y*v1.y + v1.z*v1.z + v1.w*v1.w;
    #pragma unroll
    for (int o = 16; o; o >>= 1) {
        s  += __shfl_xor_sync(0xffffffffu, s,  o);
        ss += __shfl_xor_sync(0xffffffffu, ss, o);
    }
    float mu  = s * (1.0f / 256.0f);
    float var = ss * (1.0f / 256.0f) - mu * mu;
    float rs  = rsqrtf(var + 1e-5f);

    const float4* pg = (const float4*)gamma;
    const float4* pb = (const float4*)beta;
    float4 g0 = pg[lane], g1 = pg[lane + 32];
    float4 b0 = pb[lane], b1 = pb[lane + 32];

    float r0[4] = { (v0.x-mu)*rs*g0.x+b0.x, (v0.y-mu)*rs*g0.y+b0.y,
                    (v0.z-mu)*rs*g0.z+b0.z, (v0.w-mu)*rs*g0.w+b0.w };
    float r1[4] = { (v1.x-mu)*rs*g1.x+b1.x, (v1.y-mu)*rs*g1.y+b1.y,
                    (v1.z-mu)*rs*g1.z+b1.z, (v1.w-mu)*rs*g1.w+b1.w };

    __half* base = outh + (size_t)tok * (2 * CDIM);
    #pragma unroll
    for (int g = 0; g < 2; g++) {
        float* rv = g ? r1 : r0;
        int c = g * 128 + lane * 4;
        __half2 h01, h23, l01, l23;
        hsplit(rv[0], h01.x, l01.x); hsplit(rv[1], h01.y, l01.y);
        hsplit(rv[2], h23.x, l23.x); hsplit(rv[3], h23.y, l23.y);
        *(__half2*)(base + c)            = h01;
        *(__half2*)(base + c + 2)        = h23;
        *(__half2*)(base + CDIM + c)     = l01;
        *(__half2*)(base + CDIM + c + 2) = l23;
    }
}

// ---------------- HMMA GEMM: 128x128 tile, BK=64, fp16 2-term A-split ----------------
// A [M, 2K] fp16 (hi|lo), Bw [N, K] fp16. acc = Ahi*B + Alo*B. B tile reused per pair.
// EPI 0: outh = split(gelu(acc + bias)); EPI 1: outf = res + acc + bias; EPI 2: outf = acc + bias
#define HG_SMEM 65536

template<int EPI>
__global__ __launch_bounds__(256, 2) void hgemm2(
    const __half* __restrict__ A,
    const __half* __restrict__ Bw,
    const float* __restrict__ bias,
    const float* __restrict__ res,
    float* __restrict__ outf,
    __half* __restrict__ outh,
    int M, int N, int K)
{
    extern __shared__ char smem[];
    const uint32_t sAb = smem_u32(smem);            // 2 x 16KB
    const uint32_t sBb = sAb + 32768;               // 2 x 16KB

    const int tid  = threadIdx.x;
    const int lane = tid & 31;
    const int wid  = tid >> 5;
    const int wm   = wid >> 1;       // 0..3
    const int wn   = wid & 1;        // 0..1
    const int row0 = blockIdx.y * 128;
    const int col0 = blockIdx.x * 128;
    const size_t ld2k = 2 * (size_t)K;
    const int nch = 2 * (K / 64);    // hi|lo passes per 64-K chunk

    float acc[2][8][4];
    #pragma unroll
    for (int a = 0; a < 2; a++)
        #pragma unroll
        for (int b = 0; b < 8; b++)
            #pragma unroll
            for (int c = 0; c < 4; c++) acc[a][b][c] = 0.f;

    // A chunk for pass g: col = (g&1)*K + (g>>1)*64 ; buffer g&1
    auto issueA = [&](int g) {
        int coff = (g & 1) * K + (g >> 1) * 64;
        uint32_t sa = sAb + (g & 1) * 16384;
        #pragma unroll
        for (int i = 0; i < 4; i++) {
            int id = tid + i * 256;
            int r = id >> 3, kg = id & 7;
            int sg = kg ^ (r & 7);
            cpa16(sa + (uint32_t)(r * 128 + sg * 16),
                  A + (size_t)(row0 + r) * ld2k + coff + kg * 8);
        }
    };
    // B chunk c: col = c*64 ; buffer c&1 (used by passes g=2c and 2c+1)
    auto issueB = [&](int c) {
        uint32_t sb = sBb + (c & 1) * 16384;
        #pragma unroll
        for (int i = 0; i < 4; i++) {
            int id = tid + i * 256;
            int r = id >> 3, kg = id & 7;
            int sg = kg ^ (r & 7);
            cpa16(sb + (uint32_t)(r * 128 + sg * 16),
                  Bw + (size_t)(col0 + r) * K + c * 64 + kg * 8);
        }
    };

    issueA(0); issueB(0); CP_COMMIT();
    for (int g = 0; g < nch; g++) {
        if (g + 1 < nch) {
            issueA(g + 1);
            if (((g + 1) & 1) == 0) issueB((g + 1) >> 1);
            CP_COMMIT();
            CP_WAIT1();
        } else {
            CP_WAIT0();
        }
        __syncthreads();

        const uint32_t aB = sAb + (g & 1) * 16384;
        const uint32_t bB = sBb + ((g >> 1) & 1) * 16384;
        #pragma unroll
        for (int kt = 0; kt < 4; kt++) {
            uint32_t a[2][4], b[4][4];
            const int kg = kt * 2 + (lane >> 4);
            #pragma unroll
            for (int mt = 0; mt < 2; mt++) {
                int r  = wm * 32 + mt * 16 + (lane & 15);
                int sg = kg ^ (r & 7);
                ldsm4(a[mt], aB + (uint32_t)(r * 128 + sg * 16));
            }
            #pragma unroll
            for (int nb = 0; nb < 4; nb++) {
                int r  = wn * 64 + nb * 16 + (lane & 15);
                int sg = kg ^ (r & 7);
                ldsm4(b[nb], bB + (uint32_t)(r * 128 + sg * 16));
            }
            #pragma unroll
            for (int mt = 0; mt < 2; mt++)
                #pragma unroll
                for (int nb = 0; nb < 4; nb++) {
                    mma16816(acc[mt][2 * nb],     a[mt], b[nb][0], b[nb][2]);
                    mma16816(acc[mt][2 * nb + 1], a[mt], b[nb][1], b[nb][3]);
                }
        }
        __syncthreads();
    }

    // epilogue
    const int g4 = lane >> 2, q = lane & 3;
    #pragma unroll
    for (int mt = 0; mt < 2; mt++) {
        #pragma unroll
        for (int half = 0; half < 2; half++) {
            int row = row0 + wm * 32 + mt * 16 + g4 + half * 8;
            #pragma unroll
            for (int nt = 0; nt < 8; nt++) {
                int col = col0 + wn * 64 + nt * 8 + q * 2;
                float v0 = acc[mt][nt][half * 2 + 0] + bias[col];
                float v1 = acc[mt][nt][half * 2 + 1] + bias[col + 1];
                if (EPI == 2) {
                    *(float2*)(outf + (size_t)row * N + col) = make_float2(v0, v1);
                } else if (EPI == 1) {
                    const float2 rv = *(const float2*)(res + (size_t)row * N + col);
                    *(float2*)(outf + (size_t)row * N + col) =
                        make_float2(v0 + rv.x, v1 + rv.y);
                } else {
                    v0 = gelu_exact(v0);
                    v1 = gelu_exact(v1);
                    __half2 hp, lp;
                    hsplit(v0, hp.x, lp.x);
                    hsplit(v1, hp.y, lp.y);
                    __half* hr = outh + (size_t)row * 2 * N + col;
                    *(__half2*)hr       = hp;
                    *(__half2*)(hr + N) = lp;
                }
            }
        }
    }
}

// ---------------- attention: one CTA per window, one warp per head ----------------
#define KPAD 36
#define VPAD 33
#define SM_KH   0
#define SM_VH   (NHEAD*SWIN*KPAD)
#define SM_AINT (SM_VH + NHEAD*SWIN*VPAD)
#define ATT_SMEM ((SM_AINT + 2*SWIN) * 4)

__global__ __launch_bounds__(256) void attn_kernel(
    const float* __restrict__ qkv,    // [NTOK, 768] (q|k|v)
    const float* __restrict__ btab,   // [169, 8]
    __half* __restrict__ o_h)         // [NTOK, 512] hi|lo
{
    extern __shared__ float sm[];
    float* kh  = sm + SM_KH;
    float* vh  = sm + SM_VH;
    int* tsrc  = (int*)(sm + SM_AINT);
    int* regid = tsrc + SWIN;

    const int tid  = threadIdx.x;
    const int lane = tid & 31;
    const int h    = tid >> 5;

    const int win = blockIdx.x;
    const int b   = win >> 6;
    const int wq  = win & 63;
    const int wy  = wq >> 3;
    const int wx  = wq & 7;

    if (tid < SWIN) {
        int i = tid / 7, j = tid - i * 7;
        int y  = wy * 7 + i;
        int xx = wx * 7 + j;
        int y0 = y  + SHIFTS; if (y0 >= IMG) y0 -= IMG;
        int x0 = xx + SHIFTS; if (x0 >= IMG) x0 -= IMG;
        tsrc[tid] = b * (IMG * IMG) + y0 * IMG + x0;
        int rc = (y <= 48) ? 0 : ((y <= 52) ? 1 : 2);
        regid[tid] = (xx <= 48) ? rc * 3 : ((xx >= 53) ? rc * 3 + 2 : 0);
    }
    __syncthreads();

    float* kw = kh + h * (SWIN * KPAD);
    float* vw = vh + h * (SWIN * VPAD);
    {
        const int hc = h * 32 + lane;
        for (int s = 0; s < SWIN; s++) {
            size_t g = (size_t)tsrc[s] * (3 * CDIM);
            kw[s * KPAD + lane] = qkv[g + CDIM     + hc];
            vw[s * VPAD + lane] = qkv[g + 2 * CDIM + hc];
        }
    }
    __syncwarp();

    const int t1  = lane;
    const int t2  = lane + 32;
    const bool v2 = (t2 < SWIN);
    const int t2c = v2 ? t2 : 48;
    const int it1 = t1 / 7,  jt1 = t1 - it1 * 7;
    const int it2 = t2c / 7, jt2 = t2c - it2 * 7;
    const int r1  = regid[t1];
    const int r2  = regid[t2c];

    for (int s = 0; s < SWIN; s++) {
        float qd = qkv[(size_t)tsrc[s] * (3 * CDIM) + h * 32 + lane] * QSCALE;

        float a1 = 0.f, a2 = 0.f;
        #pragma unroll
        for (int d4 = 0; d4 < 8; d4++) {
            float4 k1 = *(const float4*)&kw[t1  * KPAD + d4 * 4];
            float4 k2 = *(const float4*)&kw[t2c * KPAD + d4 * 4];
            float q0 = __shfl_sync(0xffffffffu, qd, d4 * 4 + 0);
            float q1 = __shfl_sync(0xffffffffu, qd, d4 * 4 + 1);
            float q2 = __shfl_sync(0xffffffffu, qd, d4 * 4 + 2);
            float q3 = __shfl_sync(0xffffffffu, qd, d4 * 4 + 3);
            a1 = fmaf(q0, k1.x, a1); a1 = fmaf(q1, k1.y, a1);
            a1 = fmaf(q2, k1.z, a1); a1 = fmaf(q3, k1.w, a1);
            a2 = fmaf(q0, k2.x, a2); a2 = fmaf(q1, k2.y, a2);
            a2 = fmaf(q2, k2.z, a2); a2 = fmaf(q3, k2.w, a2);
        }

        int i1 = s / 7, j1 = s - i1 * 7;
        int rs = regid[s];
        {
            int ridx = (i1 - it1 + 6) * 13 + (j1 - jt1 + 6);
            a1 += btab[ridx * NHEAD + h];
            if (rs != r1) a1 -= 100.0f;
        }
        if (v2) {
            int ridx = (i1 - it2 + 6) * 13 + (j1 - jt2 + 6);
            a2 += btab[ridx * NHEAD + h];
            if (rs != r2) a2 -= 100.0f;
        } else {
            a2 = -1e30f;
        }

        float m = fmaxf(a1, a2);
        #pragma unroll
        for (int o = 16; o; o >>= 1) m = fmaxf(m, __shfl_xor_sync(0xffffffffu, m, o));
        float e1 = __expf(a1 - m);
        float e2 = v2 ? __expf(a2 - m) : 0.0f;
        float sum = e1 + e2;
        #pragma unroll
        for (int o = 16; o; o >>= 1) sum += __shfl_xor_sync(0xffffffffu, sum, o);
        float inv = 1.0f / sum;
        float p1 = e1 * inv;
        float p2 = e2 * inv;

        float oa = 0.f;
        #pragma unroll
        for (int t = 0; t < 32; t++) {
            float av = __shfl_sync(0xffffffffu, p1, t);
            oa = fmaf(av, vw[t * VPAD + lane], oa);
        }
        #pragma unroll
        for (int t = 32; t < SWIN; t++) {
            float av = __shfl_sync(0xffffffffu, p2, t - 32);
            oa = fmaf(av, vw[t * VPAD + lane], oa);
        }
        __half hi, lo;
        hsplit(oa, hi, lo);
        size_t ob = (size_t)tsrc[s] * (2 * CDIM) + h * 32 + lane;
        o_h[ob]        = hi;
        o_h[ob + CDIM] = lo;
    }
}

// ---------------- launch ----------------
extern "C" void kernel_launch(void* const* d_in, const int* in_sizes, int n_in,
                              void* d_out, int out_size)
{
    const float* x      = (const float*)d_in[0];
    const float* gamma  = (const float*)d_in[1];
    const float* beta   = (const float*)d_in[2];
    const float* qkv_w  = (const float*)d_in[3];
    const float* qkv_b  = (const float*)d_in[4];
    const float* proj_w = (const float*)d_in[5];
    const float* proj_b = (const float*)d_in[6];
    const float* btab   = (const float*)d_in[7];
    const float* w1     = (const float*)d_in[8];
    const float* b1     = (const float*)d_in[9];
    const float* w2     = (const float*)d_in[10];
    const float* b2     = (const float*)d_in[11];
    float* out = (float*)d_out;

    __half *xnh, *oh, *xn2h, *hh, *wq, *wp, *w1h, *w2h;
    float *qkv, *x1;
    cudaGetSymbolAddress((void**)&xnh,  g_xnh);
    cudaGetSymbolAddress((void**)&oh,   g_oh);
    cudaGetSymbolAddress((void**)&xn2h, g_xn2h);
    cudaGetSymbolAddress((void**)&hh,   g_hh);
    cudaGetSymbolAddress((void**)&wq,   g_wq);
    cudaGetSymbolAddress((void**)&wp,   g_wp);
    cudaGetSymbolAddress((void**)&w1h,  g_w1h);
    cudaGetSymbolAddress((void**)&w2h,  g_w2h);
    cudaGetSymbolAddress((void**)&qkv,  g_qkv);
    cudaGetSymbolAddress((void**)&x1,   g_x1);

    cudaFuncSetAttribute(hgemm2<0>, cudaFuncAttributeMaxDynamicSharedMemorySize, HG_SMEM);
    cudaFuncSetAttribute(hgemm2<1>, cudaFuncAttributeMaxDynamicSharedMemorySize, HG_SMEM);
    cudaFuncSetAttribute(hgemm2<2>, cudaFuncAttributeMaxDynamicSharedMemorySize, HG_SMEM);
    cudaFuncSetAttribute(attn_kernel, cudaFuncAttributeMaxDynamicSharedMemorySize, ATT_SMEM);

    // weight prep (fp16 transpose to [N,K])
    wprep_t<<<(CDIM * 3 * CDIM + 255) / 256, 256>>>(qkv_w,  wq,  CDIM, 3 * CDIM);
    wprep_t<<<(CDIM * CDIM     + 255) / 256, 256>>>(proj_w, wp,  CDIM, CDIM);
    wprep_t<<<(CDIM * NMLP     + 255) / 256, 256>>>(w1,     w1h, CDIM, NMLP);
    wprep_t<<<(NMLP * CDIM     + 255) / 256, 256>>>(w2,     w2h, NMLP, CDIM);

    // 1) LN1(x) -> fp16 hi|lo
    ln_split_kernel<<<NTOK / 8, 256>>>(x, gamma, beta, xnh);
    // 2) qkv = xn @ qkv_w + qkv_b   (fp32 out)
    hgemm2<2><<<dim3(3 * CDIM / 128, NTOK / 128), 256, HG_SMEM>>>(
        xnh, wq, qkv_b, nullptr, qkv, nullptr, NTOK, 3 * CDIM, CDIM);
    // 3) windowed attention -> fp16 hi|lo
    attn_kernel<<<BATCH * NWIN, 256, ATT_SMEM>>>(qkv, btab, oh);
    // 4) x1 = x + o @ proj_w + proj_b
    hgemm2<1><<<dim3(CDIM / 128, NTOK / 128), 256, HG_SMEM>>>(
        oh, wp, proj_b, x, x1, nullptr, NTOK, CDIM, CDIM);
    // 5) LN2(x1) -> fp16 hi|lo
    ln_split_kernel<<<NTOK / 8, 256>>>(x1, gamma, beta, xn2h);
    // 6) h = gelu(xn2 @ w1 + b1) -> fp16 hi|lo
    hgemm2<0><<<dim3(NMLP / 128, NTOK / 128), 256, HG_SMEM>>>(
        xn2h, w1h, b1, nullptr, nullptr, hh, NTOK, NMLP, CDIM);
    // 7) out = x1 + h @ w2 + b2
    hgemm2<1><<<dim3(CDIM / 128, NTOK / 128), 256, HG_SMEM>>>(
        hh, w2h, b2, x1, out, nullptr, NTOK, CDIM, NMLP);
}